// round 15
// baseline (speedup 1.0000x reference)
#include <cuda_runtime.h>
#include <cuda_bf16.h>
#include <cstdint>

// Problem constants
#define BB 16
#define KK 256
#define ZZ 128
#define HH 128
#define NROWS (BB * KK)   // 4096

// fp32 scratch (K2 inputs)
__device__ __align__(16) float g_m1z[NROWS * ZZ];
__device__ __align__(16) float g_m2z[NROWS * ZZ];

// mma-fragment-layout operand storage (u32 = bf16x2 along k)
// A tile (16 rows x 8 kpairs) = 256 u32: [hi 32 lanes x 4 regs | lo ...]
// B tile ( 8 cols x 8 kpairs) = 128 u32: [hi 32 lanes x 2 regs | lo ...]
__device__ __align__(16) unsigned g_zA [256 * 8  * 256];  // z   A-frags (2 MB)
__device__ __align__(16) unsigned g_xA [256 * 16 * 256];  // X   A-frags (4 MB)
__device__ __align__(16) unsigned g_wB [32  * 8  * 128];  // [W1;W2] B-frags
__device__ __align__(16) unsigned g_wuB[16  * 16 * 128];  // Wu  B-frags

// ---------------------------------------------------------------------------
// helpers
// ---------------------------------------------------------------------------
__device__ __forceinline__ void split2(float x0, float x1,
                                       unsigned &hi, unsigned &lo)
{
    float2 v = make_float2(x0, x1);
    __nv_bfloat162 h = __float22bfloat162_rn(v);
    float2 hf = __bfloat1622float2(h);
    __nv_bfloat162 l = __float22bfloat162_rn(make_float2(v.x - hf.x, v.y - hf.y));
    hi = *reinterpret_cast<unsigned*>(&h);
    lo = *reinterpret_cast<unsigned*>(&l);
}

// address (hi element) of A-operand (row, kpair) in fragment layout
__device__ __forceinline__ int a_addr(int row, int kp, int nkt)
{
    int mt = row >> 4, r = row & 15;
    int kt = kp >> 3,  kq = kp & 7;
    int lane = ((r & 7) << 2) | (kq & 3);
    int reg  = (r >> 3) | ((kq >> 2) << 1);
    return (mt * nkt + kt) * 256 + lane * 4 + reg;   // lo at +128
}

// address (hi element) of B-operand (n, kpair) in fragment layout
__device__ __forceinline__ int b_addr(int n, int kp, int nkt)
{
    int nt = n >> 3, gn = n & 7;
    int kt = kp >> 3, kq = kp & 7;
    int lane = (gn << 2) | (kq & 3);
    int reg  = kq >> 2;
    return (nt * nkt + kt) * 128 + lane * 2 + reg;   // lo at +64
}

__device__ __forceinline__ void mma_bf16(float c[4],
    unsigned a0, unsigned a1, unsigned a2, unsigned a3,
    unsigned b0, unsigned b1)
{
    asm volatile(
        "mma.sync.aligned.m16n8k16.row.col.f32.bf16.bf16.f32 "
        "{%0,%1,%2,%3}, {%4,%5,%6,%7}, {%8,%9}, {%0,%1,%2,%3};"
        : "+f"(c[0]), "+f"(c[1]), "+f"(c[2]), "+f"(c[3])
        : "r"(a0), "r"(a1), "r"(a2), "r"(a3), "r"(b0), "r"(b1));
}

__device__ __forceinline__ void cp_async16(unsigned dst_smem, const void* src)
{
    asm volatile("cp.async.cg.shared.global [%0], [%1], 16;"
                 :: "r"(dst_smem), "l"(src));
}
__device__ __forceinline__ void cp_commit()
{
    asm volatile("cp.async.commit_group;");
}
__device__ __forceinline__ void cp_wait2()
{
    asm volatile("cp.async.wait_group 2;");
}

// ---------------------------------------------------------------------------
// P0: split z, [W1;W2], Wu into bf16 hi/lo fragment layouts.
//   tasks: z 262144, Wcat 16384, Wu 16384  -> 294912 = 1152 * 256
// ---------------------------------------------------------------------------
__global__ __launch_bounds__(256) void p0_split(
    const float* __restrict__ z,
    const float* __restrict__ W1, const float* __restrict__ W2,
    const float* __restrict__ Wu)
{
    int idx = blockIdx.x * 256 + threadIdx.x;
    if (idx < NROWS * 64) {
        float2 v = ((const float2*)z)[idx];
        unsigned hi, lo; split2(v.x, v.y, hi, lo);
        int row = idx >> 6, kp = idx & 63;
        int a1 = a_addr(row, kp, 8);
        g_zA[a1] = hi; g_zA[a1 + 128] = lo;
        int a2 = a_addr(row, kp, 16);
        g_xA[a2] = hi; g_xA[a2 + 128] = lo;
    } else if (idx < NROWS * 64 + 256 * 64) {
        int i = idx - NROWS * 64;
        int n = i >> 6, kp = i & 63;
        const float* Wr = (n < 128) ? (W1 + n * 128) : (W2 + (n - 128) * 128);
        unsigned hi, lo; split2(Wr[2 * kp], Wr[2 * kp + 1], hi, lo);
        int b = b_addr(n, kp, 8);
        g_wB[b] = hi; g_wB[b + 64] = lo;
    } else if (idx < NROWS * 64 + 256 * 64 + 128 * 128) {
        int i = idx - NROWS * 64 - 256 * 64;
        int h = i >> 7, kp = i & 127;
        unsigned hi, lo; split2(Wu[h * 256 + 2 * kp], Wu[h * 256 + 2 * kp + 1], hi, lo);
        int b = b_addr(h, kp, 16);
        g_wuB[b] = hi; g_wuB[b + 64] = lo;
    }
}

// ---------------------------------------------------------------------------
// K1': [m1z | m2z] = z @ [W1;W2]^T + bias  (3-pass bf16 split mma)
// grid (64, 8), 256 threads = 8 warps (4m x 2n). Warp tile 16m x 16n,
// block tile 64m x 32n, K = 128 (8 ksteps).
// cp.async 4-stage smem pipeline: 6 KB/stage (A 4 KB + B 2 KB), depth-3
// lead hides L2 latency without register-allocator involvement.
// ---------------------------------------------------------------------------
__global__ __launch_bounds__(256) void k1_mma(
    const float* __restrict__ b1, const float* __restrict__ b2)
{
    __shared__ __align__(16) unsigned sA[4][1024];  // [stage][mt 0..3][256]
    __shared__ __align__(16) unsigned sB[4][512];   // [stage][nt 0..3][128]

    const int tid  = threadIdx.x;
    const int lane = tid & 31;
    const int wid  = tid >> 5;
    const int wm   = wid >> 1, wn = wid & 1;
    const int g    = lane >> 2, t = lane & 3;
    const int mtb  = blockIdx.x * 4;
    const int ntb  = blockIdx.y * 4;
    const int row0 = blockIdx.x * 64 + wm * 16;
    const int n0   = blockIdx.y * 32 + wn * 16;

    auto load_stage = [&](int ks, int st) {
#pragma unroll
        for (int i0 = 0; i0 < 384; i0 += 256) {
            int i = i0 + tid;
            if (i < 384) {
                if (i < 256) {
                    int mt = i >> 6, off = (i & 63) * 4;
                    unsigned dst = (unsigned)__cvta_generic_to_shared(
                        &sA[st][mt * 256 + off]);
                    cp_async16(dst, &g_zA[((mtb + mt) * 8 + ks) * 256 + off]);
                } else {
                    int j = i - 256;
                    int nt = j >> 5, off = (j & 31) * 4;
                    unsigned dst = (unsigned)__cvta_generic_to_shared(
                        &sB[st][nt * 128 + off]);
                    cp_async16(dst, &g_wB[((ntb + nt) * 8 + ks) * 128 + off]);
                }
            }
        }
    };

    float c[2][4];
#pragma unroll
    for (int nt = 0; nt < 2; nt++)
#pragma unroll
        for (int q = 0; q < 4; q++) c[nt][q] = 0.f;

    load_stage(0, 0); cp_commit();
    load_stage(1, 1); cp_commit();
    load_stage(2, 2); cp_commit();

    for (int ks = 0; ks < 8; ks++) {
        cp_wait2();
        __syncthreads();
        const int st = ks & 3;

        uint4 ah = *(const uint4*)&sA[st][wm * 256 + lane * 4];
        uint4 al = *(const uint4*)&sA[st][wm * 256 + 128 + lane * 4];
        uint2 bh0 = *(const uint2*)&sB[st][(wn * 2) * 128 + lane * 2];
        uint2 bl0 = *(const uint2*)&sB[st][(wn * 2) * 128 + 64 + lane * 2];
        uint2 bh1 = *(const uint2*)&sB[st][(wn * 2 + 1) * 128 + lane * 2];
        uint2 bl1 = *(const uint2*)&sB[st][(wn * 2 + 1) * 128 + 64 + lane * 2];

        mma_bf16(c[0], ah.x, ah.y, ah.z, ah.w, bh0.x, bh0.y);
        mma_bf16(c[0], ah.x, ah.y, ah.z, ah.w, bl0.x, bl0.y);
        mma_bf16(c[0], al.x, al.y, al.z, al.w, bh0.x, bh0.y);
        mma_bf16(c[1], ah.x, ah.y, ah.z, ah.w, bh1.x, bh1.y);
        mma_bf16(c[1], ah.x, ah.y, ah.z, ah.w, bl1.x, bl1.y);
        mma_bf16(c[1], al.x, al.y, al.z, al.w, bh1.x, bh1.y);

        __syncthreads();
        if (ks < 5) load_stage(ks + 3, (ks + 3) & 3);
        cp_commit();
    }

    const bool second = (n0 >= 128);
    float* __restrict__ dst = second ? g_m2z : g_m1z;
    const float* __restrict__ bias = second ? b2 : b1;
    const int nbase = second ? (n0 - 128) : n0;

#pragma unroll
    for (int nt = 0; nt < 2; nt++) {
        int n = nbase + nt * 8 + 2 * t;
        float bv0 = bias[n], bv1 = bias[n + 1];
        int r = row0 + g;
        dst[r * 128 + n]           = c[nt][0] + bv0;
        dst[r * 128 + n + 1]       = c[nt][1] + bv1;
        dst[(r + 8) * 128 + n]     = c[nt][2] + bv0;
        dst[(r + 8) * 128 + n + 1] = c[nt][3] + bv1;
    }
}

// ---------------------------------------------------------------------------
// K2: relu(m1z[b,i,c] + max_{j:P[b,j,i]!=0} m2z[b,j,c]); writes bf16 hi/lo
// message half of X in fragment layout. grid (16 i-tiles, 16 batches),
// 256 threads. c4 = tid&31 -> 4 channels ; sg = tid>>5 -> i = i0+sg*2+{0,1}
// ---------------------------------------------------------------------------
__global__ __launch_bounds__(256) void k2_maskmax(const int* __restrict__ P)
{
    __shared__ unsigned smask[256];   // low 16 bits used

    const int tid  = threadIdx.x;
    const int b    = blockIdx.y;
    const int i0   = blockIdx.x * 16;
    const int lane = tid & 31;
    const int wrp  = tid >> 5;

    for (int jp = wrp; jp < 128; jp += 8) {
        int j  = 2 * jp + (lane >> 4);
        int io = lane & 15;
        int v  = P[((b * 256 + j) * 256) + i0 + io];
        unsigned word = __ballot_sync(0xffffffffu, v != 0);
        if (lane == 0) {
            smask[2 * jp]     = word & 0xffffu;
            smask[2 * jp + 1] = word >> 16;
        }
    }
    __syncthreads();

    const int c4 = tid & 31;
    const int sg = tid >> 5;

    float4 mx0 = make_float4(-3.0e38f, -3.0e38f, -3.0e38f, -3.0e38f);
    float4 mx1 = mx0;

    const float4* m2 = (const float4*)g_m2z + (size_t)b * 256 * 32;

#pragma unroll 8
    for (int j = 0; j < 256; j++) {
        float4 v = m2[j * 32 + c4];
        unsigned mw = smask[j] >> (sg * 2);
        if (mw & 1u) {
            mx0.x = fmaxf(mx0.x, v.x); mx0.y = fmaxf(mx0.y, v.y);
            mx0.z = fmaxf(mx0.z, v.z); mx0.w = fmaxf(mx0.w, v.w);
        }
        if (mw & 2u) {
            mx1.x = fmaxf(mx1.x, v.x); mx1.y = fmaxf(mx1.y, v.y);
            mx1.z = fmaxf(mx1.z, v.z); mx1.w = fmaxf(mx1.w, v.w);
        }
    }

    const float4* m1 = (const float4*)g_m1z + (size_t)b * 256 * 32;

#pragma unroll
    for (int s = 0; s < 2; s++) {
        int i = i0 + sg * 2 + s;
        float4 mxv = s ? mx1 : mx0;
        float4 a = m1[i * 32 + c4];
        float4 o;
        o.x = fmaxf(a.x + mxv.x, 0.f); o.y = fmaxf(a.y + mxv.y, 0.f);
        o.z = fmaxf(a.z + mxv.z, 0.f); o.w = fmaxf(a.w + mxv.w, 0.f);

        int grow = b * 256 + i;
        unsigned h0, l0, h1, l1;
        split2(o.x, o.y, h0, l0);
        split2(o.z, o.w, h1, l1);
        int kp = 64 + 2 * c4;            // message kpairs
        int a0 = a_addr(grow, kp, 16);
        int a1 = a_addr(grow, kp + 1, 16);
        g_xA[a0] = h0; g_xA[a0 + 128] = l0;
        g_xA[a1] = h1; g_xA[a1 + 128] = l1;
    }
}

// ---------------------------------------------------------------------------
// K3': out = relu(X @ Wu^T + bu), X = [z | m] in fragment layout, K = 256
// (16 ksteps). grid (64, 4), 256 threads = 8 warps (4m x 2n),
// warp tile 16m x 16n, block tile 64m x 32n. Same cp.async pipeline as K1'.
// ---------------------------------------------------------------------------
__global__ __launch_bounds__(256) void k3_mma(
    const float* __restrict__ bu, float* __restrict__ out)
{
    __shared__ __align__(16) unsigned sA[4][1024];
    __shared__ __align__(16) unsigned sB[4][512];

    const int tid  = threadIdx.x;
    const int lane = tid & 31;
    const int wid  = tid >> 5;
    const int wm   = wid >> 1, wn = wid & 1;
    const int g    = lane >> 2, t = lane & 3;
    const int mtb  = blockIdx.x * 4;
    const int ntb  = blockIdx.y * 4;
    const int row0 = blockIdx.x * 64 + wm * 16;
    const int n0   = blockIdx.y * 32 + wn * 16;

    auto load_stage = [&](int ks, int st) {
#pragma unroll
        for (int i0 = 0; i0 < 384; i0 += 256) {
            int i = i0 + tid;
            if (i < 384) {
                if (i < 256) {
                    int mt = i >> 6, off = (i & 63) * 4;
                    unsigned dst = (unsigned)__cvta_generic_to_shared(
                        &sA[st][mt * 256 + off]);
                    cp_async16(dst, &g_xA[((mtb + mt) * 16 + ks) * 256 + off]);
                } else {
                    int j = i - 256;
                    int nt = j >> 5, off = (j & 31) * 4;
                    unsigned dst = (unsigned)__cvta_generic_to_shared(
                        &sB[st][nt * 128 + off]);
                    cp_async16(dst, &g_wuB[((ntb + nt) * 16 + ks) * 128 + off]);
                }
            }
        }
    };

    float c[2][4];
#pragma unroll
    for (int nt = 0; nt < 2; nt++)
#pragma unroll
        for (int q = 0; q < 4; q++) c[nt][q] = 0.f;

    load_stage(0, 0); cp_commit();
    load_stage(1, 1); cp_commit();
    load_stage(2, 2); cp_commit();

    for (int ks = 0; ks < 16; ks++) {
        cp_wait2();
        __syncthreads();
        const int st = ks & 3;

        uint4 ah = *(const uint4*)&sA[st][wm * 256 + lane * 4];
        uint4 al = *(const uint4*)&sA[st][wm * 256 + 128 + lane * 4];
        uint2 bh0 = *(const uint2*)&sB[st][(wn * 2) * 128 + lane * 2];
        uint2 bl0 = *(const uint2*)&sB[st][(wn * 2) * 128 + 64 + lane * 2];
        uint2 bh1 = *(const uint2*)&sB[st][(wn * 2 + 1) * 128 + lane * 2];
        uint2 bl1 = *(const uint2*)&sB[st][(wn * 2 + 1) * 128 + 64 + lane * 2];

        mma_bf16(c[0], ah.x, ah.y, ah.z, ah.w, bh0.x, bh0.y);
        mma_bf16(c[0], ah.x, ah.y, ah.z, ah.w, bl0.x, bl0.y);
        mma_bf16(c[0], al.x, al.y, al.z, al.w, bh0.x, bh0.y);
        mma_bf16(c[1], ah.x, ah.y, ah.z, ah.w, bh1.x, bh1.y);
        mma_bf16(c[1], ah.x, ah.y, ah.z, ah.w, bl1.x, bl1.y);
        mma_bf16(c[1], al.x, al.y, al.z, al.w, bh1.x, bh1.y);

        __syncthreads();
        if (ks < 13) load_stage(ks + 3, (ks + 3) & 3);
        cp_commit();
    }

#pragma unroll
    for (int nt = 0; nt < 2; nt++) {
        int n = n0 + nt * 8 + 2 * t;
        float bv0 = bu[n], bv1 = bu[n + 1];
        int r = row0 + g;
        out[r * 128 + n]           = fmaxf(c[nt][0] + bv0, 0.f);
        out[r * 128 + n + 1]       = fmaxf(c[nt][1] + bv1, 0.f);
        out[(r + 8) * 128 + n]     = fmaxf(c[nt][2] + bv0, 0.f);
        out[(r + 8) * 128 + n + 1] = fmaxf(c[nt][3] + bv1, 0.f);
    }
}

// ---------------------------------------------------------------------------
// Launch. Inputs (metadata order): z, P, W1, b1, W2, b2, Wu, bu.
// ---------------------------------------------------------------------------
extern "C" void kernel_launch(void* const* d_in, const int* in_sizes, int n_in,
                              void* d_out, int out_size)
{
    const float* z  = (const float*)d_in[0];
    const int*   P  = (const int*)  d_in[1];
    const float* W1 = (const float*)d_in[2];
    const float* b1 = (const float*)d_in[3];
    const float* W2 = (const float*)d_in[4];
    const float* b2 = (const float*)d_in[5];
    const float* Wu = (const float*)d_in[6];
    const float* bu = (const float*)d_in[7];
    float* out = (float*)d_out;

    p0_split<<<1152, 256>>>(z, W1, W2, Wu);

    dim3 g1(64, 8);
    k1_mma<<<g1, 256>>>(b1, b2);

    dim3 g2(16, 16);
    k2_maskmax<<<g2, 256>>>(P);

    dim3 g3(64, 4);
    k3_mma<<<g3, 256>>>(bu, out);
}

// round 16
// speedup vs baseline: 1.2300x; 1.2300x over previous
#include <cuda_runtime.h>
#include <cuda_bf16.h>
#include <cstdint>

// Problem constants
#define BB 16
#define KK 256
#define ZZ 128
#define HH 128
#define NROWS (BB * KK)   // 4096
#define NBLK 256          // co-resident persistent blocks (2/SM on 148+ SMs)

// fp32 scratch (K2 inputs)
__device__ __align__(16) float g_m1z[NROWS * ZZ];
__device__ __align__(16) float g_m2z[NROWS * ZZ];

// mma-fragment-layout operand storage (u32 = bf16x2 along k)
// A tile (16 rows x 8 kpairs) = 256 u32: [hi 32 lanes x 4 regs | lo ...]
// B tile ( 8 cols x 8 kpairs) = 128 u32: [hi 32 lanes x 2 regs | lo ...]
__device__ __align__(16) unsigned g_zA [256 * 8  * 256];  // z   A-frags (2 MB)
__device__ __align__(16) unsigned g_xA [256 * 16 * 256];  // X   A-frags (4 MB)
__device__ __align__(16) unsigned g_wB [32  * 8  * 128];  // [W1;W2] B-frags
__device__ __align__(16) unsigned g_wuB[16  * 16 * 128];  // Wu  B-frags

// ticket barrier counters (monotonic; correct across graph replays, no reset)
__device__ unsigned g_barsite[4];

// ---------------------------------------------------------------------------
// helpers
// ---------------------------------------------------------------------------
__device__ __forceinline__ void grid_barrier(int site)
{
    __syncthreads();
    if (threadIdx.x == 0) {
        __threadfence();
        unsigned v = atomicAdd(&g_barsite[site], 1u);
        unsigned target = (v / gridDim.x + 1u) * gridDim.x;
        while (*(volatile unsigned*)&g_barsite[site] < target)
            __nanosleep(32);
        __threadfence();
    }
    __syncthreads();
}

__device__ __forceinline__ void split2(float x0, float x1,
                                       unsigned &hi, unsigned &lo)
{
    float2 v = make_float2(x0, x1);
    __nv_bfloat162 h = __float22bfloat162_rn(v);
    float2 hf = __bfloat1622float2(h);
    __nv_bfloat162 l = __float22bfloat162_rn(make_float2(v.x - hf.x, v.y - hf.y));
    hi = *reinterpret_cast<unsigned*>(&h);
    lo = *reinterpret_cast<unsigned*>(&l);
}

// address (hi element) of A-operand (row, kpair) in fragment layout
__device__ __forceinline__ int a_addr(int row, int kp, int nkt)
{
    int mt = row >> 4, r = row & 15;
    int kt = kp >> 3,  kq = kp & 7;
    int lane = ((r & 7) << 2) | (kq & 3);
    int reg  = (r >> 3) | ((kq >> 2) << 1);
    return (mt * nkt + kt) * 256 + lane * 4 + reg;   // lo at +128
}

// address (hi element) of B-operand (n, kpair) in fragment layout
__device__ __forceinline__ int b_addr(int n, int kp, int nkt)
{
    int nt = n >> 3, gn = n & 7;
    int kt = kp >> 3, kq = kp & 7;
    int lane = (gn << 2) | (kq & 3);
    int reg  = kq >> 2;
    return (nt * nkt + kt) * 128 + lane * 2 + reg;   // lo at +64
}

__device__ __forceinline__ void mma_bf16(float c[4],
    unsigned a0, unsigned a1, unsigned a2, unsigned a3,
    unsigned b0, unsigned b1)
{
    asm volatile(
        "mma.sync.aligned.m16n8k16.row.col.f32.bf16.bf16.f32 "
        "{%0,%1,%2,%3}, {%4,%5,%6,%7}, {%8,%9}, {%0,%1,%2,%3};"
        : "+f"(c[0]), "+f"(c[1]), "+f"(c[2]), "+f"(c[3])
        : "r"(a0), "r"(a1), "r"(a2), "r"(a3), "r"(b0), "r"(b1));
}

__device__ __forceinline__ void cp_async16(unsigned dst_smem, const void* src)
{
    asm volatile("cp.async.cg.shared.global [%0], [%1], 16;"
                 :: "r"(dst_smem), "l"(src));
}
__device__ __forceinline__ void cp_commit()
{
    asm volatile("cp.async.commit_group;");
}
__device__ __forceinline__ void cp_wait2()
{
    asm volatile("cp.async.wait_group 2;");
}
__device__ __forceinline__ void cp_wait0()
{
    asm volatile("cp.async.wait_group 0;");
}

// ---------------------------------------------------------------------------
// GEMM tile bodies (cp.async 4-stage pipeline, warp tile 16m x 16n,
// block tile 64m x 32n, 8 warps). NKT = ksteps (8 for k1, 16 for k3).
// ---------------------------------------------------------------------------
template <int NKT>
__device__ __forceinline__ void gemm_tile(
    unsigned (*sA)[1024], unsigned (*sB)[512],
    const unsigned* __restrict__ gA, const unsigned* __restrict__ gB,
    int bx, int by,
    const float* __restrict__ bias0, const float* __restrict__ bias1,
    float* __restrict__ dst0, float* __restrict__ dst1,
    bool relu)
{
    const int tid  = threadIdx.x;
    const int lane = tid & 31;
    const int wid  = tid >> 5;
    const int wm   = wid >> 1, wn = wid & 1;
    const int g    = lane >> 2, t = lane & 3;
    const int mtb  = bx * 4;
    const int ntb  = by * 4;
    const int row0 = bx * 64 + wm * 16;
    const int n0   = by * 32 + wn * 16;

    auto load_stage = [&](int ks, int st) {
#pragma unroll
        for (int i0 = 0; i0 < 384; i0 += 256) {
            int i = i0 + tid;
            if (i < 384) {
                if (i < 256) {
                    int mt = i >> 6, off = (i & 63) * 4;
                    unsigned dst = (unsigned)__cvta_generic_to_shared(
                        &sA[st][mt * 256 + off]);
                    cp_async16(dst, &gA[((mtb + mt) * NKT + ks) * 256 + off]);
                } else {
                    int j = i - 256;
                    int nt = j >> 5, off = (j & 31) * 4;
                    unsigned dst = (unsigned)__cvta_generic_to_shared(
                        &sB[st][nt * 128 + off]);
                    cp_async16(dst, &gB[((ntb + nt) * NKT + ks) * 128 + off]);
                }
            }
        }
    };

    float c[2][4];
#pragma unroll
    for (int nt = 0; nt < 2; nt++)
#pragma unroll
        for (int q = 0; q < 4; q++) c[nt][q] = 0.f;

    load_stage(0, 0); cp_commit();
    load_stage(1, 1); cp_commit();
    load_stage(2, 2); cp_commit();

    for (int ks = 0; ks < NKT; ks++) {
        cp_wait2();
        __syncthreads();
        const int st = ks & 3;

        uint4 ah = *(const uint4*)&sA[st][wm * 256 + lane * 4];
        uint4 al = *(const uint4*)&sA[st][wm * 256 + 128 + lane * 4];
        uint2 bh0 = *(const uint2*)&sB[st][(wn * 2) * 128 + lane * 2];
        uint2 bl0 = *(const uint2*)&sB[st][(wn * 2) * 128 + 64 + lane * 2];
        uint2 bh1 = *(const uint2*)&sB[st][(wn * 2 + 1) * 128 + lane * 2];
        uint2 bl1 = *(const uint2*)&sB[st][(wn * 2 + 1) * 128 + 64 + lane * 2];

        mma_bf16(c[0], ah.x, ah.y, ah.z, ah.w, bh0.x, bh0.y);
        mma_bf16(c[0], ah.x, ah.y, ah.z, ah.w, bl0.x, bl0.y);
        mma_bf16(c[0], al.x, al.y, al.z, al.w, bh0.x, bh0.y);
        mma_bf16(c[1], ah.x, ah.y, ah.z, ah.w, bh1.x, bh1.y);
        mma_bf16(c[1], ah.x, ah.y, ah.z, ah.w, bl1.x, bl1.y);
        mma_bf16(c[1], al.x, al.y, al.z, al.w, bh1.x, bh1.y);

        __syncthreads();
        if (ks < NKT - 3) load_stage(ks + 3, (ks + 3) & 3);
        cp_commit();
    }
    cp_wait0();       // drain before smem reuse by the next tile/phase
    __syncthreads();

    const bool second = (n0 >= 128);
    float* __restrict__ dst = second ? dst1 : dst0;
    const float* __restrict__ bias = second ? bias1 : bias0;
    const int nbase = second ? (n0 - 128) : n0;

#pragma unroll
    for (int nt = 0; nt < 2; nt++) {
        int n = nbase + nt * 8 + 2 * t;
        float bv0 = bias[n], bv1 = bias[n + 1];
        int r = row0 + g;
        float o0 = c[nt][0] + bv0, o1 = c[nt][1] + bv1;
        float o2 = c[nt][2] + bv0, o3 = c[nt][3] + bv1;
        if (relu) {
            o0 = fmaxf(o0, 0.f); o1 = fmaxf(o1, 0.f);
            o2 = fmaxf(o2, 0.f); o3 = fmaxf(o3, 0.f);
        }
        dst[r * 128 + n]           = o0;
        dst[r * 128 + n + 1]       = o1;
        dst[(r + 8) * 128 + n]     = o2;
        dst[(r + 8) * 128 + n + 1] = o3;
    }
}

// ---------------------------------------------------------------------------
// Fused persistent kernel: phase0 split -> phase1 k1 -> phase2 k2 -> phase3 k3
// 256 blocks x 256 threads, all co-resident (2 blocks/SM), ticket barriers.
// ---------------------------------------------------------------------------
__global__ __launch_bounds__(256, 2) void fused_all(
    const float* __restrict__ z,  const int* __restrict__ P,
    const float* __restrict__ W1, const float* __restrict__ b1,
    const float* __restrict__ W2, const float* __restrict__ b2,
    const float* __restrict__ Wu, const float* __restrict__ bu,
    float* __restrict__ out)
{
    __shared__ __align__(16) unsigned sA[4][1024];  // 16 KB
    __shared__ __align__(16) unsigned sB[4][512];   //  8 KB
    __shared__ unsigned smask[256];                 //  1 KB

    const int tid = threadIdx.x;
    const int bid = blockIdx.x;

    // ================= phase 0: bf16 hi/lo fragment split =================
    for (int idx = bid * 256 + tid; idx < NROWS * 64 + 256 * 64 + 128 * 128;
         idx += NBLK * 256) {
        if (idx < NROWS * 64) {
            float2 v = ((const float2*)z)[idx];
            unsigned hi, lo; split2(v.x, v.y, hi, lo);
            int row = idx >> 6, kp = idx & 63;
            int a1 = a_addr(row, kp, 8);
            g_zA[a1] = hi; g_zA[a1 + 128] = lo;
            int a2 = a_addr(row, kp, 16);
            g_xA[a2] = hi; g_xA[a2 + 128] = lo;
        } else if (idx < NROWS * 64 + 256 * 64) {
            int i = idx - NROWS * 64;
            int n = i >> 6, kp = i & 63;
            const float* Wr = (n < 128) ? (W1 + n * 128) : (W2 + (n - 128) * 128);
            unsigned hi, lo; split2(Wr[2 * kp], Wr[2 * kp + 1], hi, lo);
            int b = b_addr(n, kp, 8);
            g_wB[b] = hi; g_wB[b + 64] = lo;
        } else {
            int i = idx - NROWS * 64 - 256 * 64;
            int h = i >> 7, kp = i & 127;
            unsigned hi, lo;
            split2(Wu[h * 256 + 2 * kp], Wu[h * 256 + 2 * kp + 1], hi, lo);
            int b = b_addr(h, kp, 16);
            g_wuB[b] = hi; g_wuB[b + 64] = lo;
        }
    }
    grid_barrier(0);

    // ================= phase 1: [m1z|m2z] = z @ [W1;W2]^T + bias ==========
    for (int tile = bid; tile < 512; tile += NBLK)
        gemm_tile<8>(sA, sB, g_zA, g_wB, tile & 63, tile >> 6,
                     b1, b2, g_m1z, g_m2z, /*relu=*/false);
    grid_barrier(1);

    // ================= phase 2: masked max message ========================
    {
        const int b    = bid >> 4;
        const int i0   = (bid & 15) * 16;
        const int lane = tid & 31;
        const int wrp  = tid >> 5;

        for (int jp = wrp; jp < 128; jp += 8) {
            int j  = 2 * jp + (lane >> 4);
            int io = lane & 15;
            int v  = P[((b * 256 + j) * 256) + i0 + io];
            unsigned word = __ballot_sync(0xffffffffu, v != 0);
            if (lane == 0) {
                smask[2 * jp]     = word & 0xffffu;
                smask[2 * jp + 1] = word >> 16;
            }
        }
        __syncthreads();

        const int c4 = tid & 31;
        const int sg = tid >> 5;

        float4 mx0 = make_float4(-3.0e38f, -3.0e38f, -3.0e38f, -3.0e38f);
        float4 mx1 = mx0;

        const float4* m2 = (const float4*)g_m2z + (size_t)b * 256 * 32;

#pragma unroll 8
        for (int j = 0; j < 256; j++) {
            float4 v = m2[j * 32 + c4];
            unsigned mw = smask[j] >> (sg * 2);
            if (mw & 1u) {
                mx0.x = fmaxf(mx0.x, v.x); mx0.y = fmaxf(mx0.y, v.y);
                mx0.z = fmaxf(mx0.z, v.z); mx0.w = fmaxf(mx0.w, v.w);
            }
            if (mw & 2u) {
                mx1.x = fmaxf(mx1.x, v.x); mx1.y = fmaxf(mx1.y, v.y);
                mx1.z = fmaxf(mx1.z, v.z); mx1.w = fmaxf(mx1.w, v.w);
            }
        }

        const float4* m1 = (const float4*)g_m1z + (size_t)b * 256 * 32;

#pragma unroll
        for (int s = 0; s < 2; s++) {
            int i = i0 + sg * 2 + s;
            float4 mxv = s ? mx1 : mx0;
            float4 a = m1[i * 32 + c4];
            float4 o;
            o.x = fmaxf(a.x + mxv.x, 0.f); o.y = fmaxf(a.y + mxv.y, 0.f);
            o.z = fmaxf(a.z + mxv.z, 0.f); o.w = fmaxf(a.w + mxv.w, 0.f);

            int grow = b * 256 + i;
            unsigned h0, l0, h1, l1;
            split2(o.x, o.y, h0, l0);
            split2(o.z, o.w, h1, l1);
            int kp = 64 + 2 * c4;            // message kpairs
            int a0 = a_addr(grow, kp, 16);
            int a1 = a_addr(grow, kp + 1, 16);
            g_xA[a0] = h0; g_xA[a0 + 128] = l0;
            g_xA[a1] = h1; g_xA[a1 + 128] = l1;
        }
    }
    grid_barrier(2);

    // ================= phase 3: out = relu(X @ Wu^T + bu) =================
    gemm_tile<16>(sA, sB, g_xA, g_wuB, bid & 63, bid >> 6,
                  bu, bu, out, out, /*relu=*/true);
}

// ---------------------------------------------------------------------------
// Launch. Inputs (metadata order): z, P, W1, b1, W2, b2, Wu, bu.
// ---------------------------------------------------------------------------
extern "C" void kernel_launch(void* const* d_in, const int* in_sizes, int n_in,
                              void* d_out, int out_size)
{
    const float* z  = (const float*)d_in[0];
    const int*   P  = (const int*)  d_in[1];
    const float* W1 = (const float*)d_in[2];
    const float* b1 = (const float*)d_in[3];
    const float* W2 = (const float*)d_in[4];
    const float* b2 = (const float*)d_in[5];
    const float* Wu = (const float*)d_in[6];
    const float* bu = (const float*)d_in[7];
    float* out = (float*)d_out;

    fused_all<<<NBLK, 256>>>(z, P, W1, b1, W2, b2, Wu, bu, out);
}

// round 17
// speedup vs baseline: 1.2624x; 1.0263x over previous
#include <cuda_runtime.h>
#include <cuda_bf16.h>
#include <cstdint>

// Problem constants
#define BB 16
#define KK 256
#define ZZ 128
#define HH 128
#define NROWS (BB * KK)   // 4096
#define NBLK 256          // co-resident persistent blocks (2/SM on 148+ SMs)

// fp32 scratch (K2 inputs)
__device__ __align__(16) float g_m1z[NROWS * ZZ];
__device__ __align__(16) float g_m2z[NROWS * ZZ];

// mma-fragment-layout operand storage (u32 = bf16x2 along k)
// A tile (16 rows x 8 kpairs) = 256 u32: [hi 32 lanes x 4 regs | lo ...]
// B tile ( 8 cols x 8 kpairs) = 128 u32: [hi 32 lanes x 2 regs | lo ...]
__device__ __align__(16) unsigned g_zA [256 * 8  * 256];  // z   A-frags (2 MB)
__device__ __align__(16) unsigned g_xA [256 * 16 * 256];  // X   A-frags (4 MB)
__device__ __align__(16) unsigned g_wB [32  * 8  * 128];  // [W1;W2] B-frags
__device__ __align__(16) unsigned g_wuB[16  * 16 * 128];  // Wu  B-frags

// ticket barrier counters (monotonic; correct across graph replays, no reset)
__device__ unsigned g_barsite[4];

// ---------------------------------------------------------------------------
// helpers
// ---------------------------------------------------------------------------
__device__ __forceinline__ void grid_barrier(int site)
{
    __syncthreads();
    if (threadIdx.x == 0) {
        __threadfence();
        unsigned v = atomicAdd(&g_barsite[site], 1u);
        unsigned target = (v / gridDim.x + 1u) * gridDim.x;
        while (*(volatile unsigned*)&g_barsite[site] < target)
            __nanosleep(32);
        __threadfence();
    }
    __syncthreads();
}

__device__ __forceinline__ void split2(float x0, float x1,
                                       unsigned &hi, unsigned &lo)
{
    float2 v = make_float2(x0, x1);
    __nv_bfloat162 h = __float22bfloat162_rn(v);
    float2 hf = __bfloat1622float2(h);
    __nv_bfloat162 l = __float22bfloat162_rn(make_float2(v.x - hf.x, v.y - hf.y));
    hi = *reinterpret_cast<unsigned*>(&h);
    lo = *reinterpret_cast<unsigned*>(&l);
}

// address (hi element) of A-operand (row, kpair) in fragment layout
__device__ __forceinline__ int a_addr(int row, int kp, int nkt)
{
    int mt = row >> 4, r = row & 15;
    int kt = kp >> 3,  kq = kp & 7;
    int lane = ((r & 7) << 2) | (kq & 3);
    int reg  = (r >> 3) | ((kq >> 2) << 1);
    return (mt * nkt + kt) * 256 + lane * 4 + reg;   // lo at +128
}

// address (hi element) of B-operand (n, kpair) in fragment layout
__device__ __forceinline__ int b_addr(int n, int kp, int nkt)
{
    int nt = n >> 3, gn = n & 7;
    int kt = kp >> 3, kq = kp & 7;
    int lane = (gn << 2) | (kq & 3);
    int reg  = kq >> 2;
    return (nt * nkt + kt) * 128 + lane * 2 + reg;   // lo at +64
}

__device__ __forceinline__ void mma_bf16(float c[4],
    unsigned a0, unsigned a1, unsigned a2, unsigned a3,
    unsigned b0, unsigned b1)
{
    asm volatile(
        "mma.sync.aligned.m16n8k16.row.col.f32.bf16.bf16.f32 "
        "{%0,%1,%2,%3}, {%4,%5,%6,%7}, {%8,%9}, {%0,%1,%2,%3};"
        : "+f"(c[0]), "+f"(c[1]), "+f"(c[2]), "+f"(c[3])
        : "r"(a0), "r"(a1), "r"(a2), "r"(a3), "r"(b0), "r"(b1));
}

__device__ __forceinline__ void cp_async16(unsigned dst_smem, const void* src)
{
    asm volatile("cp.async.cg.shared.global [%0], [%1], 16;"
                 :: "r"(dst_smem), "l"(src));
}
__device__ __forceinline__ void cp_commit()
{
    asm volatile("cp.async.commit_group;");
}
__device__ __forceinline__ void cp_wait2()
{
    asm volatile("cp.async.wait_group 2;");
}
__device__ __forceinline__ void cp_wait0()
{
    asm volatile("cp.async.wait_group 0;");
}

// ---------------------------------------------------------------------------
// GEMM tile body. cp.async 4-stage pipeline, 8 warps arranged 4m x 2n.
// NKT = ksteps. NTN = m16n8 ntiles per warp (4 -> block 64m x 64n for phase1,
// 2 -> block 64m x 32n for phase3). One __syncthreads per kstep.
// ---------------------------------------------------------------------------
template <int NKT, int NTN>
__device__ __forceinline__ void gemm_tile(
    unsigned (*sA)[1024], unsigned (*sB)[1024],
    const unsigned* __restrict__ gA, const unsigned* __restrict__ gB,
    int bx, int by,
    const float* __restrict__ bias0, const float* __restrict__ bias1,
    float* __restrict__ dst0, float* __restrict__ dst1,
    bool relu)
{
    const int tid  = threadIdx.x;
    const int lane = tid & 31;
    const int wid  = tid >> 5;
    const int wm   = wid >> 1, wn = wid & 1;
    const int g    = lane >> 2, t = lane & 3;
    const int mtb  = bx * 4;
    const int ntb  = by * (2 * NTN);
    const int row0 = bx * 64 + wm * 16;
    const int n0   = by * (16 * NTN) + wn * (8 * NTN);
    constexpr int LD_TOT = 256 + 64 * NTN;   // cp16 ops per stage

    auto load_stage = [&](int ks, int st) {
#pragma unroll
        for (int i0 = 0; i0 < LD_TOT; i0 += 256) {
            int i = i0 + tid;
            if (i < LD_TOT) {
                if (i < 256) {
                    int mt = i >> 6, off = (i & 63) * 4;
                    unsigned dst = (unsigned)__cvta_generic_to_shared(
                        &sA[st][mt * 256 + off]);
                    cp_async16(dst, &gA[((mtb + mt) * NKT + ks) * 256 + off]);
                } else {
                    int j = i - 256;
                    int nt2 = j >> 5, off = (j & 31) * 4;
                    unsigned dst = (unsigned)__cvta_generic_to_shared(
                        &sB[st][nt2 * 128 + off]);
                    cp_async16(dst, &gB[((ntb + nt2) * NKT + ks) * 128 + off]);
                }
            }
        }
    };

    float c[NTN][4];
#pragma unroll
    for (int nt = 0; nt < NTN; nt++)
#pragma unroll
        for (int q = 0; q < 4; q++) c[nt][q] = 0.f;

    load_stage(0, 0); cp_commit();
    load_stage(1, 1); cp_commit();
    load_stage(2, 2); cp_commit();

    for (int ks = 0; ks < NKT; ks++) {
        cp_wait2();
        __syncthreads();
        // prefetch stage ks+3 (overwrites stage (ks-1)&3, whose reads were
        // ordered before this barrier by the previous iteration)
        if (ks < NKT - 3) load_stage(ks + 3, (ks + 3) & 3);
        cp_commit();

        const int st = ks & 3;
        uint4 ah = *(const uint4*)&sA[st][wm * 256 + lane * 4];
        uint4 al = *(const uint4*)&sA[st][wm * 256 + 128 + lane * 4];
#pragma unroll
        for (int nt = 0; nt < NTN; nt++) {
            uint2 bh = *(const uint2*)&sB[st][(wn * NTN + nt) * 128 + lane * 2];
            uint2 bl = *(const uint2*)&sB[st][(wn * NTN + nt) * 128 + 64 + lane * 2];
            mma_bf16(c[nt], ah.x, ah.y, ah.z, ah.w, bh.x, bh.y);
            mma_bf16(c[nt], ah.x, ah.y, ah.z, ah.w, bl.x, bl.y);
            mma_bf16(c[nt], al.x, al.y, al.z, al.w, bh.x, bh.y);
        }
    }
    cp_wait0();       // drain before smem reuse by the next phase
    __syncthreads();

    const bool second = (n0 >= 128);
    float* __restrict__ dst = second ? dst1 : dst0;
    const float* __restrict__ bias = second ? bias1 : bias0;
    const int nbase = second ? (n0 - 128) : n0;

#pragma unroll
    for (int nt = 0; nt < NTN; nt++) {
        int n = nbase + nt * 8 + 2 * t;
        float bv0 = bias[n], bv1 = bias[n + 1];
        int r = row0 + g;
        float o0 = c[nt][0] + bv0, o1 = c[nt][1] + bv1;
        float o2 = c[nt][2] + bv0, o3 = c[nt][3] + bv1;
        if (relu) {
            o0 = fmaxf(o0, 0.f); o1 = fmaxf(o1, 0.f);
            o2 = fmaxf(o2, 0.f); o3 = fmaxf(o3, 0.f);
        }
        dst[r * 128 + n]           = o0;
        dst[r * 128 + n + 1]       = o1;
        dst[(r + 8) * 128 + n]     = o2;
        dst[(r + 8) * 128 + n + 1] = o3;
    }
}

// ---------------------------------------------------------------------------
// Fused persistent kernel: phase0 split -> phase1 k1 -> phase2 k2 -> phase3 k3
// 256 blocks x 256 threads, all co-resident (2 blocks/SM), ticket barriers.
// ---------------------------------------------------------------------------
__global__ __launch_bounds__(256, 2) void fused_all(
    const float* __restrict__ z,  const int* __restrict__ P,
    const float* __restrict__ W1, const float* __restrict__ b1,
    const float* __restrict__ W2, const float* __restrict__ b2,
    const float* __restrict__ Wu, const float* __restrict__ bu,
    float* __restrict__ out)
{
    __shared__ __align__(16) unsigned sA[4][1024];  // 16 KB
    __shared__ __align__(16) unsigned sB[4][1024];  // 16 KB
    __shared__ unsigned smask[256];                 //  1 KB

    const int tid = threadIdx.x;
    const int bid = blockIdx.x;

    // ================= phase 0: bf16 hi/lo fragment split =================
    for (int idx = bid * 256 + tid; idx < NROWS * 64 + 256 * 64 + 128 * 128;
         idx += NBLK * 256) {
        if (idx < NROWS * 64) {
            float2 v = ((const float2*)z)[idx];
            unsigned hi, lo; split2(v.x, v.y, hi, lo);
            int row = idx >> 6, kp = idx & 63;
            int a1 = a_addr(row, kp, 8);
            g_zA[a1] = hi; g_zA[a1 + 128] = lo;
            int a2 = a_addr(row, kp, 16);
            g_xA[a2] = hi; g_xA[a2 + 128] = lo;
        } else if (idx < NROWS * 64 + 256 * 64) {
            int i = idx - NROWS * 64;
            int n = i >> 6, kp = i & 63;
            const float* Wr = (n < 128) ? (W1 + n * 128) : (W2 + (n - 128) * 128);
            unsigned hi, lo; split2(Wr[2 * kp], Wr[2 * kp + 1], hi, lo);
            int b = b_addr(n, kp, 8);
            g_wB[b] = hi; g_wB[b + 64] = lo;
        } else {
            int i = idx - NROWS * 64 - 256 * 64;
            int h = i >> 7, kp = i & 127;
            unsigned hi, lo;
            split2(Wu[h * 256 + 2 * kp], Wu[h * 256 + 2 * kp + 1], hi, lo);
            int b = b_addr(h, kp, 16);
            g_wuB[b] = hi; g_wuB[b + 64] = lo;
        }
    }
    grid_barrier(0);

    // ====== phase 1: [m1z|m2z] = z @ [W1;W2]^T + bias (one 64x64 tile) =====
    gemm_tile<8, 4>(sA, sB, g_zA, g_wB, bid & 63, bid >> 6,
                    b1, b2, g_m1z, g_m2z, /*relu=*/false);
    grid_barrier(1);

    // ================= phase 2: masked max message ========================
    {
        const int b    = bid >> 4;
        const int i0   = (bid & 15) * 16;
        const int lane = tid & 31;
        const int wrp  = tid >> 5;

        for (int jp = wrp; jp < 128; jp += 8) {
            int j  = 2 * jp + (lane >> 4);
            int io = lane & 15;
            int v  = P[((b * 256 + j) * 256) + i0 + io];
            unsigned word = __ballot_sync(0xffffffffu, v != 0);
            if (lane == 0) {
                smask[2 * jp]     = word & 0xffffu;
                smask[2 * jp + 1] = word >> 16;
            }
        }
        __syncthreads();

        const int c4 = tid & 31;
        const int sg = tid >> 5;

        float4 mx0 = make_float4(-3.0e38f, -3.0e38f, -3.0e38f, -3.0e38f);
        float4 mx1 = mx0;

        const float4* m2 = (const float4*)g_m2z + (size_t)b * 256 * 32;

#pragma unroll 8
        for (int j = 0; j < 256; j++) {
            float4 v = m2[j * 32 + c4];
            unsigned mw = smask[j] >> (sg * 2);
            if (mw & 1u) {
                mx0.x = fmaxf(mx0.x, v.x); mx0.y = fmaxf(mx0.y, v.y);
                mx0.z = fmaxf(mx0.z, v.z); mx0.w = fmaxf(mx0.w, v.w);
            }
            if (mw & 2u) {
                mx1.x = fmaxf(mx1.x, v.x); mx1.y = fmaxf(mx1.y, v.y);
                mx1.z = fmaxf(mx1.z, v.z); mx1.w = fmaxf(mx1.w, v.w);
            }
        }

        const float4* m1 = (const float4*)g_m1z + (size_t)b * 256 * 32;

#pragma unroll
        for (int s = 0; s < 2; s++) {
            int i = i0 + sg * 2 + s;
            float4 mxv = s ? mx1 : mx0;
            float4 a = m1[i * 32 + c4];
            float4 o;
            o.x = fmaxf(a.x + mxv.x, 0.f); o.y = fmaxf(a.y + mxv.y, 0.f);
            o.z = fmaxf(a.z + mxv.z, 0.f); o.w = fmaxf(a.w + mxv.w, 0.f);

            int grow = b * 256 + i;
            unsigned h0, l0, h1, l1;
            split2(o.x, o.y, h0, l0);
            split2(o.z, o.w, h1, l1);
            int kp = 64 + 2 * c4;            // message kpairs
            int a0 = a_addr(grow, kp, 16);
            int a1 = a_addr(grow, kp + 1, 16);
            g_xA[a0] = h0; g_xA[a0 + 128] = l0;
            g_xA[a1] = h1; g_xA[a1 + 128] = l1;
        }
    }
    grid_barrier(2);

    // ============ phase 3: out = relu(X @ Wu^T + bu) (64x32 tile) ==========
    gemm_tile<16, 2>(sA, sB, g_xA, g_wuB, bid & 63, bid >> 6,
                     bu, bu, out, out, /*relu=*/true);
}

// ---------------------------------------------------------------------------
// Launch. Inputs (metadata order): z, P, W1, b1, W2, b2, Wu, bu.
// ---------------------------------------------------------------------------
extern "C" void kernel_launch(void* const* d_in, const int* in_sizes, int n_in,
                              void* d_out, int out_size)
{
    const float* z  = (const float*)d_in[0];
    const int*   P  = (const int*)  d_in[1];
    const float* W1 = (const float*)d_in[2];
    const float* b1 = (const float*)d_in[3];
    const float* W2 = (const float*)d_in[4];
    const float* b2 = (const float*)d_in[5];
    const float* Wu = (const float*)d_in[6];
    const float* bu = (const float*)d_in[7];
    float* out = (float*)d_out;

    fused_all<<<NBLK, 256>>>(z, P, W1, b1, W2, b2, Wu, bu, out);
}